// round 1
// baseline (speedup 1.0000x reference)
#include <cuda_runtime.h>
#include <math.h>

// Problem constants (fixed shapes for this problem)
#define C 128           // channel dim (QDIM = TDIM = QK = V = 128)
#define L 54            // H*W = 6*9
#define NTOK 8          // query tokens / output tokens
#define NH 8            // heads
#define HD 16           // head dim
#define MAXB 8192

#define BPB 8           // batches per block in attention kernel

// padded shared-memory strides (avoid 32-bank conflicts on 128-float rows)
#define TGT_S 132
#define QK_S  132
#define A_S   132       // K2 operand stride

// Scratch (device globals: allocation-free rule)
__device__ float g_qk[64 * 128];                 // [tok][head][c] * scale
__device__ float g_att[(size_t)MAXB * NTOK * C]; // attention output (pre-Wp)

// ---------------------------------------------------------------------------
// K0: prep. LN(query); q = qn@Wq + bq; qk[t,h,c] = 0.25 * sum_j Wk[c, h*16+j] * q[t, h*16+j]
// ---------------------------------------------------------------------------
__global__ void prep_kernel(const float* __restrict__ q_in,
                            const float* __restrict__ g1, const float* __restrict__ b1,
                            const float* __restrict__ Wq, const float* __restrict__ bq,
                            const float* __restrict__ Wk) {
    __shared__ float s_qn[NTOK * C];
    __shared__ float s_q[NTOK * C];
    int tid = threadIdx.x;
    int warp = tid >> 5, lane = tid & 31;

    // LayerNorm: warp w handles token row w (8 warps, 256 threads)
    {
        int t = warp;
        float4 v = *reinterpret_cast<const float4*>(q_in + t * C + lane * 4);
        float s = v.x + v.y + v.z + v.w;
        #pragma unroll
        for (int o = 16; o; o >>= 1) s += __shfl_xor_sync(0xffffffffu, s, o);
        float mean = s * (1.0f / 128.0f);
        float dx = v.x - mean, dy = v.y - mean, dz = v.z - mean, dw = v.w - mean;
        float sq = dx * dx + dy * dy + dz * dz + dw * dw;
        #pragma unroll
        for (int o = 16; o; o >>= 1) sq += __shfl_xor_sync(0xffffffffu, sq, o);
        float inv = rsqrtf(sq * (1.0f / 128.0f) + 1e-5f);
        int c = lane * 4;
        s_qn[t * C + c + 0] = dx * inv * g1[c + 0] + b1[c + 0];
        s_qn[t * C + c + 1] = dy * inv * g1[c + 1] + b1[c + 1];
        s_qn[t * C + c + 2] = dz * inv * g1[c + 2] + b1[c + 2];
        s_qn[t * C + c + 3] = dw * inv * g1[c + 3] + b1[c + 3];
    }
    __syncthreads();

    // q = qn @ Wq + bq  (8x128 outputs)
    for (int idx = tid; idx < NTOK * C; idx += 256) {
        int t = idx >> 7, o = idx & 127;
        float acc = bq[o];
        #pragma unroll 4
        for (int i = 0; i < C; i++) acc += s_qn[t * C + i] * Wq[i * C + o];
        s_q[idx] = acc;
    }
    __syncthreads();

    // qk[t,h,c] = scale * sum_j Wk[c, h*16+j] * q[t, h*16+j]
    for (int idx = tid; idx < 64 * C; idx += 256) {
        int t = idx >> 10, h = (idx >> 7) & 7, c = idx & 127;
        const float* qh = s_q + t * C + h * HD;
        const float* wk = Wk + c * C + h * HD;
        float acc = 0.0f;
        #pragma unroll
        for (int j = 0; j < HD; j++) acc += qh[j] * wk[j];
        g_qk[idx] = acc * 0.25f;   // scale = (C/NH)^-0.5 = 0.25
    }
}

// ---------------------------------------------------------------------------
// K1: per-batch fused attention.
//   dots[t,h,li] = qk[t,h,:] . tgt[l]        (bk cancels in softmax)
//   a = softmax over 9 region positions
//   w[t,h,:] = sum_li a * tgt[l]
//   att[t, h*16+j] = w[t,h,:] . Wv[:, h*16+j] + bv
// ---------------------------------------------------------------------------
__global__ __launch_bounds__(512, 1)
void attn_kernel(const float* __restrict__ tgt,
                 const float* __restrict__ Wv, const float* __restrict__ bv,
                 int B) {
    extern __shared__ float sm[];
    float* s_qk  = sm;                 // 64 rows * QK_S = 8448
    float* s_wv  = s_qk + 64 * QK_S;   // 16384  (row-major [c][o])
    float* s_bv  = s_wv + 16384;       // 128
    float* s_tgt = s_bv + 128;         // 54 rows * TGT_S = 7128
    float* s_w   = s_tgt + L * TGT_S;  // 64*128 = 8192
    float* s_p   = s_w + 64 * 128;     // 64*12 = 768 (logits -> probs)

    int tid = threadIdx.x;

    // stage qk (padded rows) and Wv into smem once per block
    for (int idx = tid; idx < 64 * 32; idx += 512) {
        int row = idx >> 5, j = idx & 31;
        reinterpret_cast<float4*>(s_qk + row * QK_S)[j] =
            reinterpret_cast<const float4*>(g_qk + row * 128)[j];
    }
    for (int i = tid; i < 4096; i += 512)
        reinterpret_cast<float4*>(s_wv)[i] = reinterpret_cast<const float4*>(Wv)[i];
    if (tid < 128) s_bv[tid] = bv[tid];
    __syncthreads();

    for (int bi = 0; bi < BPB; bi++) {
        int b = blockIdx.x * BPB + bi;
        if (b >= B) break;

        // load tgt[b] (54x128) into padded smem
        const float4* tsrc = reinterpret_cast<const float4*>(tgt + (size_t)b * L * C);
        for (int idx = tid; idx < L * 32; idx += 512) {
            int row = idx >> 5, j = idx & 31;
            reinterpret_cast<float4*>(s_tgt + row * TGT_S)[j] = tsrc[row * 32 + j];
        }
        __syncthreads();

        // dots: 64 (tok,head) combos x 9 region positions = 576 dot products of length 128
        for (int task = tid; task < 576; task += 512) {
            int th = task / 9, li = task - th * 9;
            int t = th >> 3;
            int r = (t < 2) ? t : (t - 2);
            int h0 = (r / 3) * 3, w0 = (r % 3) * 3;
            int l = (h0 + li / 3) * 9 + (w0 + li % 3);
            const float* qv = s_qk + th * QK_S;
            const float* xv = s_tgt + l * TGT_S;
            float a0 = 0, a1 = 0, a2 = 0, a3 = 0;
            #pragma unroll
            for (int c = 0; c < C; c += 4) {
                float4 a = *reinterpret_cast<const float4*>(qv + c);
                float4 x = *reinterpret_cast<const float4*>(xv + c);
                a0 += a.x * x.x; a1 += a.y * x.y; a2 += a.z * x.z; a3 += a.w * x.w;
            }
            s_p[th * 12 + li] = a0 + a1 + a2 + a3;
        }
        __syncthreads();

        // softmax over 9 per combo
        if (tid < 64) {
            float m = -1e30f;
            #pragma unroll
            for (int li = 0; li < 9; li++) m = fmaxf(m, s_p[tid * 12 + li]);
            float e[9]; float s = 0.0f;
            #pragma unroll
            for (int li = 0; li < 9; li++) { e[li] = expf(s_p[tid * 12 + li] - m); s += e[li]; }
            float inv = 1.0f / s;
            #pragma unroll
            for (int li = 0; li < 9; li++) s_p[tid * 12 + li] = e[li] * inv;
        }
        __syncthreads();

        // w[th, :] = sum_li a * tgt[l, :]  (float4 over c)
        for (int idx = tid; idx < 64 * 32; idx += 512) {
            int th = idx >> 5, c4 = (idx & 31);
            int t = th >> 3;
            int r = (t < 2) ? t : (t - 2);
            int base = (r / 3) * 27 + (r % 3) * 3;   // (h0)*9 + w0
            float4 acc = make_float4(0.f, 0.f, 0.f, 0.f);
            #pragma unroll
            for (int li = 0; li < 9; li++) {
                int l = base + (li / 3) * 9 + (li % 3);
                float a = s_p[th * 12 + li];
                float4 x = reinterpret_cast<const float4*>(s_tgt + l * TGT_S)[c4];
                acc.x += a * x.x; acc.y += a * x.y; acc.z += a * x.z; acc.w += a * x.w;
            }
            reinterpret_cast<float4*>(s_w + th * 128)[c4] = acc;
        }
        __syncthreads();

        // att[t, o] = w[t*8 + (o>>4), :] . Wv[:, o] + bv[o]
        // 512 threads -> each computes 2 outputs (t0 and t0+4) sharing Wv column reads
        {
            int o = tid & 127;
            int t0 = tid >> 7;          // 0..3
            int h = o >> 4;
            const float* w0 = s_w + (t0 * 8 + h) * 128;
            const float* w1 = s_w + ((t0 + 4) * 8 + h) * 128;
            float p0 = 0, p1 = 0, q0 = 0, q1 = 0;
            #pragma unroll
            for (int c = 0; c < C; c += 2) {
                float wv0 = s_wv[c * 128 + o];
                float wv1 = s_wv[(c + 1) * 128 + o];
                p0 += w0[c] * wv0;  p1 += w0[c + 1] * wv1;
                q0 += w1[c] * wv0;  q1 += w1[c + 1] * wv1;
            }
            float* outp = g_att + (size_t)b * NTOK * C;
            outp[t0 * C + o]       = p0 + p1 + s_bv[o];
            outp[(t0 + 4) * C + o] = q0 + q1 + s_bv[o];
        }
        __syncthreads();
    }
}

// ---------------------------------------------------------------------------
// K2: 128-row tiles of the [B*8, 128] row space.
//   X = att @ Wp + bp + shortcut(query[tok]);  Xn = LN(X);
//   H1 = gelu(Xn@Wf1+bf1);  out = X + H1@Wf2 + bf2
// 8x8 register-blocked fp32 microkernel, 256 threads (16x16).
// ---------------------------------------------------------------------------
__device__ __forceinline__ void gemm_tile_128(const float* __restrict__ A,
                                              const float* __restrict__ W,
                                              float acc[8][8], int ty, int tx) {
    #pragma unroll
    for (int i = 0; i < 8; i++)
        #pragma unroll
        for (int j = 0; j < 8; j++) acc[i][j] = 0.0f;

    for (int k = 0; k < 128; k += 4) {
        float4 a[8];
        #pragma unroll
        for (int i = 0; i < 8; i++)
            a[i] = *reinterpret_cast<const float4*>(&A[(ty * 8 + i) * A_S + k]);
        float4 b0[4], b1[4];
        #pragma unroll
        for (int kk = 0; kk < 4; kk++) {
            b0[kk] = *reinterpret_cast<const float4*>(&W[(k + kk) * 128 + tx * 8]);
            b1[kk] = *reinterpret_cast<const float4*>(&W[(k + kk) * 128 + tx * 8 + 4]);
        }
        #pragma unroll
        for (int i = 0; i < 8; i++) {
            float av[4] = {a[i].x, a[i].y, a[i].z, a[i].w};
            #pragma unroll
            for (int kk = 0; kk < 4; kk++) {
                acc[i][0] += av[kk] * b0[kk].x;
                acc[i][1] += av[kk] * b0[kk].y;
                acc[i][2] += av[kk] * b0[kk].z;
                acc[i][3] += av[kk] * b0[kk].w;
                acc[i][4] += av[kk] * b1[kk].x;
                acc[i][5] += av[kk] * b1[kk].y;
                acc[i][6] += av[kk] * b1[kk].z;
                acc[i][7] += av[kk] * b1[kk].w;
            }
        }
    }
}

__global__ __launch_bounds__(256, 1)
void ffn_kernel(const float* __restrict__ query,
                const float* __restrict__ g2, const float* __restrict__ b2,
                const float* __restrict__ Wp, const float* __restrict__ bp,
                const float* __restrict__ Wf1, const float* __restrict__ bf1,
                const float* __restrict__ Wf2, const float* __restrict__ bf2,
                float* __restrict__ out, int nrows) {
    extern __shared__ float sm[];
    float* WB = sm;                   // 16384 (weight, stride 128)
    float* P  = WB + 16384;           // 128 * A_S (operand buffer)
    float* Q  = P + 128 * A_S;        // 128 * A_S (X buffer)

    int tid = threadIdx.x;
    int ty = tid >> 4, tx = tid & 15;
    int R0 = blockIdx.x * 128;
    if (R0 >= nrows) return;

    // load att tile -> P (padded), Wp -> WB
    {
        const float4* src = reinterpret_cast<const float4*>(g_att + (size_t)R0 * C);
        for (int idx = tid; idx < 128 * 32; idx += 256) {
            int row = idx >> 5, j = idx & 31;
            reinterpret_cast<float4*>(P + row * A_S)[j] = src[row * 32 + j];
        }
        for (int i = tid; i < 4096; i += 256)
            reinterpret_cast<float4*>(WB)[i] = reinterpret_cast<const float4*>(Wp)[i];
    }
    __syncthreads();

    float acc[8][8];

    // GEMM1: X = att@Wp + bp + shortcut  -> Q
    gemm_tile_128(P, WB, acc, ty, tx);
    #pragma unroll
    for (int i = 0; i < 8; i++) {
        int r = ty * 8 + i;
        int t = r & 7;   // R0 multiple of 128 => global row % 8 == r % 8
        #pragma unroll
        for (int j = 0; j < 8; j++) {
            int c = tx * 8 + j;
            Q[r * A_S + c] = acc[i][j] + bp[c] + query[t * C + c];
        }
    }
    __syncthreads();

    // LN rows of Q -> P ; concurrently load Wf1 -> WB
    {
        int warp = tid >> 5, lane = tid & 31;
        for (int r = warp; r < 128; r += 8) {
            float4 v = *reinterpret_cast<const float4*>(&Q[r * A_S + lane * 4]);
            float s = v.x + v.y + v.z + v.w;
            #pragma unroll
            for (int o = 16; o; o >>= 1) s += __shfl_xor_sync(0xffffffffu, s, o);
            float mean = s * (1.0f / 128.0f);
            float dx = v.x - mean, dy = v.y - mean, dz = v.z - mean, dw = v.w - mean;
            float sq = dx * dx + dy * dy + dz * dz + dw * dw;
            #pragma unroll
            for (int o = 16; o; o >>= 1) sq += __shfl_xor_sync(0xffffffffu, sq, o);
            float inv = rsqrtf(sq * (1.0f / 128.0f) + 1e-5f);
            int c = lane * 4;
            float4 gg = *reinterpret_cast<const float4*>(&g2[c]);
            float4 bb = *reinterpret_cast<const float4*>(&b2[c]);
            float4 o4;
            o4.x = dx * inv * gg.x + bb.x;
            o4.y = dy * inv * gg.y + bb.y;
            o4.z = dz * inv * gg.z + bb.z;
            o4.w = dw * inv * gg.w + bb.w;
            *reinterpret_cast<float4*>(&P[r * A_S + c]) = o4;
        }
        for (int i = tid; i < 4096; i += 256)
            reinterpret_cast<float4*>(WB)[i] = reinterpret_cast<const float4*>(Wf1)[i];
    }
    __syncthreads();

    // GEMM2: H1 = gelu(Xn@Wf1 + bf1)
    gemm_tile_128(P, WB, acc, ty, tx);
    __syncthreads();   // all reads of P/WB done
    #pragma unroll
    for (int i = 0; i < 8; i++) {
        int r = ty * 8 + i;
        #pragma unroll
        for (int j = 0; j < 8; j++) {
            int c = tx * 8 + j;
            float v = acc[i][j] + bf1[c];
            P[r * A_S + c] = 0.5f * v * (1.0f + erff(v * 0.70710678118654752f));
        }
    }
    for (int i = tid; i < 4096; i += 256)
        reinterpret_cast<float4*>(WB)[i] = reinterpret_cast<const float4*>(Wf2)[i];
    __syncthreads();

    // GEMM3: out = X + H1@Wf2 + bf2
    gemm_tile_128(P, WB, acc, ty, tx);
    #pragma unroll
    for (int i = 0; i < 8; i++) {
        int r = ty * 8 + i;
        float* orow = out + (size_t)(R0 + r) * C;
        #pragma unroll
        for (int j = 0; j < 8; j++) {
            int c = tx * 8 + j;
            orow[c] = acc[i][j] + bf2[c] + Q[r * A_S + c];
        }
    }
}

// ---------------------------------------------------------------------------
extern "C" void kernel_launch(void* const* d_in, const int* in_sizes, int n_in,
                              void* d_out, int out_size) {
    const float* query = (const float*)d_in[0];
    const float* tgt   = (const float*)d_in[1];
    const float* ln1g  = (const float*)d_in[2];
    const float* ln1b  = (const float*)d_in[3];
    const float* ln2g  = (const float*)d_in[4];
    const float* ln2b  = (const float*)d_in[5];
    const float* Wq    = (const float*)d_in[6];
    const float* bq    = (const float*)d_in[7];
    const float* Wk    = (const float*)d_in[8];
    // d_in[9] = bk (cancels in softmax)
    const float* Wv    = (const float*)d_in[10];
    const float* bv    = (const float*)d_in[11];
    const float* Wp    = (const float*)d_in[12];
    const float* bp    = (const float*)d_in[13];
    const float* Wf1   = (const float*)d_in[14];
    const float* bf1   = (const float*)d_in[15];
    const float* Wf2   = (const float*)d_in[16];
    const float* bf2   = (const float*)d_in[17];

    int B = in_sizes[1] / (L * C);
    if (B > MAXB) B = MAXB;

    const int K1_SMEM = (64 * QK_S + 16384 + 128 + L * TGT_S + 64 * 128 + 64 * 12) * sizeof(float);
    const int K2_SMEM = (16384 + 2 * 128 * A_S) * sizeof(float);

    cudaFuncSetAttribute(attn_kernel, cudaFuncAttributeMaxDynamicSharedMemorySize, K1_SMEM);
    cudaFuncSetAttribute(ffn_kernel,  cudaFuncAttributeMaxDynamicSharedMemorySize, K2_SMEM);

    prep_kernel<<<1, 256>>>(query, ln1g, ln1b, Wq, bq, Wk);
    attn_kernel<<<(B + BPB - 1) / BPB, 512, K1_SMEM>>>(tgt, Wv, bv, B);

    int nrows = B * NTOK;
    ffn_kernel<<<(nrows + 127) / 128, 256, K2_SMEM>>>(query, ln2g, ln2b,
                                                      Wp, bp, Wf1, bf1, Wf2, bf2,
                                                      (float*)d_out, nrows);
}

// round 2
// speedup vs baseline: 1.3701x; 1.3701x over previous
#include <cuda_runtime.h>
#include <math.h>

// Problem constants
#define C 128
#define L 54            // 6*9
#define NTOK 8
#define MAXB 8192
#define BPB 8

// smem strides
#define W_S   132       // s_w row stride (floats)
#define WVT_S 132       // transposed Wv row stride
#define SP_S  80        // per-token softmax row stride
#define A_S   132       // ffn operand stride

// Scratch
__device__ float g_qk[64 * 128];                 // [(t*8+h)][c], pre-scaled
__device__ float g_att[(size_t)MAXB * NTOK * C];

// ---------------------------------------------------------------------------
// K0: prep. grid = 64 blocks (t*8+h), 128 threads.
//   LN(query[t]); q[t, h*16+j] = qn@Wq+bq; qk[t,h,c] = 0.25 * Wk[c, hseg].q[t,hseg]
// ---------------------------------------------------------------------------
__global__ void prep_kernel(const float* __restrict__ q_in,
                            const float* __restrict__ g1, const float* __restrict__ b1,
                            const float* __restrict__ Wq, const float* __restrict__ bq,
                            const float* __restrict__ Wk) {
    __shared__ float s_qn[128];
    __shared__ float s_qh[16];
    __shared__ float s_red[8];
    int th = blockIdx.x, t = th >> 3, h = th & 7;
    int tid = threadIdx.x, lane = tid & 31, warp = tid >> 5;

    float x = q_in[t * 128 + tid];
    float s = x;
    #pragma unroll
    for (int o = 16; o; o >>= 1) s += __shfl_xor_sync(~0u, s, o);
    if (lane == 0) s_red[warp] = s;
    __syncthreads();
    float mean = (s_red[0] + s_red[1] + s_red[2] + s_red[3]) * (1.0f / 128.0f);
    float dx = x - mean;
    float sq = dx * dx;
    #pragma unroll
    for (int o = 16; o; o >>= 1) sq += __shfl_xor_sync(~0u, sq, o);
    __syncthreads();
    if (lane == 0) s_red[warp] = sq;
    __syncthreads();
    float var = (s_red[0] + s_red[1] + s_red[2] + s_red[3]) * (1.0f / 128.0f);
    float inv = rsqrtf(var + 1e-5f);
    s_qn[tid] = dx * inv * g1[tid] + b1[tid];
    __syncthreads();

    // q[h*16+j], j = tid>>3, 8-lane partial sums
    int j = tid >> 3, seg = tid & 7;
    int o = h * 16 + j;
    float p = 0.0f;
    #pragma unroll
    for (int i = 0; i < 16; i++) p += s_qn[seg * 16 + i] * Wq[(seg * 16 + i) * 128 + o];
    #pragma unroll
    for (int off = 4; off; off >>= 1) p += __shfl_xor_sync(~0u, p, off);
    if (seg == 0) s_qh[j] = p + bq[o];
    __syncthreads();

    // qk row
    float acc = 0.0f;
    const float* wk = Wk + tid * 128 + h * 16;
    #pragma unroll
    for (int jj = 0; jj < 16; jj++) acc += s_qh[jj] * wk[jj];
    g_qk[th * 128 + tid] = acc * 0.25f;
}

// ---------------------------------------------------------------------------
// K1: fused attention, 512 threads, BPB batches per block.
//   warps (t,half): lane = (hq, c8) -> head hh = half*4+hq, c-chunks c8*4 + 32j
// ---------------------------------------------------------------------------
__global__ __launch_bounds__(512, 1)
void attn_kernel(const float* __restrict__ tgt,
                 const float* __restrict__ Wv, const float* __restrict__ bv,
                 int B) {
    extern __shared__ float sm[];
    float* s_qk  = sm;                       //  8192
    float* s_wvT = s_qk  + 64 * 128;         // 16896 (WvT[o][c], interleaved chunks)
    float* s_bv  = s_wvT + 128 * WVT_S;      //   128
    float* s_tgt = s_bv  + 128;              //  6912
    float* s_w   = s_tgt + L * 128;          //  8448
    float* s_p   = s_w   + 64 * W_S;         //   640

    int tid = threadIdx.x;
    int warp = tid >> 5, lane = tid & 31;

    // stage qk, WvT (transposed), bv
    for (int idx = tid; idx < 2048; idx += 512)
        reinterpret_cast<float4*>(s_qk)[idx] = reinterpret_cast<const float4*>(g_qk)[idx];
    for (int idx = tid; idx < 16384; idx += 512) {
        int o = idx & 127, c = idx >> 7;
        s_wvT[o * WVT_S + c] = Wv[c * 128 + o];
    }
    if (tid < 128) s_bv[tid] = bv[tid];
    __syncthreads();

    // role decomposition
    int t_tok = warp >> 1, half = warp & 1;
    int hq = lane >> 3, c8 = lane & 7;
    int hh = half * 4 + hq;
    int qrow = t_tok * 8 + hh;
    int r = (t_tok < 2) ? t_tok : (t_tok - 2);
    int base_l = (r / 3) * 27 + (r % 3) * 3;
    // region row offsets for li = 0..8
    const int loff[9] = {0, 1, 2, 9, 10, 11, 18, 19, 20};

    // Wv-phase mapping
    int tpair = lane >> 3;          // t in {tpair, tpair+4}
    int hB = warp >> 1;             // head for o-slice [8*warp, 8*warp+8)

    // preload qk chunks (static across batches)
    float4 qk4[4];
    #pragma unroll
    for (int jj = 0; jj < 4; jj++)
        qk4[jj] = *reinterpret_cast<const float4*>(s_qk + qrow * 128 + c8 * 4 + 32 * jj);

    for (int bi = 0; bi < BPB; bi++) {
        int b = blockIdx.x * BPB + bi;
        if (b >= B) break;

        // load tgt[b] into smem
        const float4* tsrc = reinterpret_cast<const float4*>(tgt + (size_t)b * L * C);
        for (int idx = tid; idx < L * 32; idx += 512)
            reinterpret_cast<float4*>(s_tgt)[idx] = tsrc[idx];
        __syncthreads();

        // ---- dots: d[li] = qk[qrow] . tgt[l], K split over 8 lanes ----
        float d[9];
        #pragma unroll
        for (int li = 0; li < 9; li++) {
            const float* row = s_tgt + (base_l + loff[li]) * 128;
            float a = 0.0f;
            #pragma unroll
            for (int jj = 0; jj < 4; jj++) {
                float4 x4 = *reinterpret_cast<const float4*>(row + c8 * 4 + 32 * jj);
                a = fmaf(qk4[jj].x, x4.x, a);
                a = fmaf(qk4[jj].y, x4.y, a);
                a = fmaf(qk4[jj].z, x4.z, a);
                a = fmaf(qk4[jj].w, x4.w, a);
            }
            d[li] = a;
        }
        #pragma unroll
        for (int off = 4; off; off >>= 1) {
            #pragma unroll
            for (int li = 0; li < 9; li++)
                d[li] += __shfl_xor_sync(~0u, d[li], off);
        }
        if (c8 == 0) {
            #pragma unroll
            for (int li = 0; li < 9; li++)
                s_p[t_tok * SP_S + hh * 9 + li] = d[li];
        }
        __syncthreads();

        // ---- softmax over 9 per (t,h): 64 threads ----
        if (tid < 64) {
            float* pp = s_p + (tid >> 3) * SP_S + (tid & 7) * 9;
            float m = -1e30f;
            #pragma unroll
            for (int li = 0; li < 9; li++) m = fmaxf(m, pp[li]);
            float e[9]; float ssum = 0.0f;
            #pragma unroll
            for (int li = 0; li < 9; li++) { e[li] = expf(pp[li] - m); ssum += e[li]; }
            float invs = 1.0f / ssum;
            #pragma unroll
            for (int li = 0; li < 9; li++) pp[li] = e[li] * invs;
        }
        __syncthreads();

        // ---- w[qrow, c-slice] = sum_li a * tgt[l, c-slice] ----
        {
            float4 w4[4];
            #pragma unroll
            for (int jj = 0; jj < 4; jj++) w4[jj] = make_float4(0.f, 0.f, 0.f, 0.f);
            #pragma unroll
            for (int li = 0; li < 9; li++) {
                float a = s_p[t_tok * SP_S + hh * 9 + li];
                const float* row = s_tgt + (base_l + loff[li]) * 128;
                #pragma unroll
                for (int jj = 0; jj < 4; jj++) {
                    float4 x4 = *reinterpret_cast<const float4*>(row + c8 * 4 + 32 * jj);
                    w4[jj].x = fmaf(a, x4.x, w4[jj].x);
                    w4[jj].y = fmaf(a, x4.y, w4[jj].y);
                    w4[jj].z = fmaf(a, x4.z, w4[jj].z);
                    w4[jj].w = fmaf(a, x4.w, w4[jj].w);
                }
            }
            #pragma unroll
            for (int jj = 0; jj < 4; jj++)
                *reinterpret_cast<float4*>(s_w + qrow * W_S + c8 * 4 + 32 * jj) = w4[jj];
        }
        __syncthreads();

        // ---- att[t, o] = w[t*8+hB, :] . Wv[:, o] + bv[o] ----
        // warp -> o in [8*warp, 8*warp+8); lane: tpair -> t in {tpair, tpair+4}, c8 chunks
        {
            float4 w4[2][4];
            #pragma unroll
            for (int tt = 0; tt < 2; tt++) {
                int t = tpair + tt * 4;
                const float* row = s_w + (t * 8 + hB) * W_S;
                #pragma unroll
                for (int jj = 0; jj < 4; jj++)
                    w4[tt][jj] = *reinterpret_cast<const float4*>(row + c8 * 4 + 32 * jj);
            }
            float acc[2][8];
            #pragma unroll
            for (int tt = 0; tt < 2; tt++)
                #pragma unroll
                for (int oo = 0; oo < 8; oo++) acc[tt][oo] = 0.0f;

            #pragma unroll
            for (int jj = 0; jj < 4; jj++) {
                #pragma unroll
                for (int oo = 0; oo < 8; oo++) {
                    float4 v4 = *reinterpret_cast<const float4*>(
                        s_wvT + (warp * 8 + oo) * WVT_S + c8 * 4 + 32 * jj);
                    #pragma unroll
                    for (int tt = 0; tt < 2; tt++) {
                        float aa = acc[tt][oo];
                        aa = fmaf(w4[tt][jj].x, v4.x, aa);
                        aa = fmaf(w4[tt][jj].y, v4.y, aa);
                        aa = fmaf(w4[tt][jj].z, v4.z, aa);
                        aa = fmaf(w4[tt][jj].w, v4.w, aa);
                        acc[tt][oo] = aa;
                    }
                }
            }
            #pragma unroll
            for (int off = 4; off; off >>= 1)
                #pragma unroll
                for (int tt = 0; tt < 2; tt++)
                    #pragma unroll
                    for (int oo = 0; oo < 8; oo++)
                        acc[tt][oo] += __shfl_xor_sync(~0u, acc[tt][oo], off);

            if (c8 == 0) {
                float4 bva = *reinterpret_cast<const float4*>(s_bv + warp * 8);
                float4 bvb = *reinterpret_cast<const float4*>(s_bv + warp * 8 + 4);
                #pragma unroll
                for (int tt = 0; tt < 2; tt++) {
                    int t = tpair + tt * 4;
                    float* op = g_att + ((size_t)b * NTOK + t) * C + warp * 8;
                    float4 o1 = make_float4(acc[tt][0] + bva.x, acc[tt][1] + bva.y,
                                            acc[tt][2] + bva.z, acc[tt][3] + bva.w);
                    float4 o2 = make_float4(acc[tt][4] + bvb.x, acc[tt][5] + bvb.y,
                                            acc[tt][6] + bvb.z, acc[tt][7] + bvb.w);
                    *reinterpret_cast<float4*>(op)     = o1;
                    *reinterpret_cast<float4*>(op + 4) = o2;
                }
            }
        }
        __syncthreads();
    }
}

// ---------------------------------------------------------------------------
// K2: FFN chain (unchanged from round 1)
// ---------------------------------------------------------------------------
__device__ __forceinline__ void gemm_tile_128(const float* __restrict__ A,
                                              const float* __restrict__ W,
                                              float acc[8][8], int ty, int tx) {
    #pragma unroll
    for (int i = 0; i < 8; i++)
        #pragma unroll
        for (int j = 0; j < 8; j++) acc[i][j] = 0.0f;

    for (int k = 0; k < 128; k += 4) {
        float4 a[8];
        #pragma unroll
        for (int i = 0; i < 8; i++)
            a[i] = *reinterpret_cast<const float4*>(&A[(ty * 8 + i) * A_S + k]);
        float4 b0[4], b1[4];
        #pragma unroll
        for (int kk = 0; kk < 4; kk++) {
            b0[kk] = *reinterpret_cast<const float4*>(&W[(k + kk) * 128 + tx * 8]);
            b1[kk] = *reinterpret_cast<const float4*>(&W[(k + kk) * 128 + tx * 8 + 4]);
        }
        #pragma unroll
        for (int i = 0; i < 8; i++) {
            float av[4] = {a[i].x, a[i].y, a[i].z, a[i].w};
            #pragma unroll
            for (int kk = 0; kk < 4; kk++) {
                acc[i][0] += av[kk] * b0[kk].x;
                acc[i][1] += av[kk] * b0[kk].y;
                acc[i][2] += av[kk] * b0[kk].z;
                acc[i][3] += av[kk] * b0[kk].w;
                acc[i][4] += av[kk] * b1[kk].x;
                acc[i][5] += av[kk] * b1[kk].y;
                acc[i][6] += av[kk] * b1[kk].z;
                acc[i][7] += av[kk] * b1[kk].w;
            }
        }
    }
}

__global__ __launch_bounds__(256, 1)
void ffn_kernel(const float* __restrict__ query,
                const float* __restrict__ g2, const float* __restrict__ b2,
                const float* __restrict__ Wp, const float* __restrict__ bp,
                const float* __restrict__ Wf1, const float* __restrict__ bf1,
                const float* __restrict__ Wf2, const float* __restrict__ bf2,
                float* __restrict__ out, int nrows) {
    extern __shared__ float sm[];
    float* WB = sm;
    float* P  = WB + 16384;
    float* Q  = P + 128 * A_S;

    int tid = threadIdx.x;
    int ty = tid >> 4, tx = tid & 15;
    int R0 = blockIdx.x * 128;
    if (R0 >= nrows) return;

    {
        const float4* src = reinterpret_cast<const float4*>(g_att + (size_t)R0 * C);
        for (int idx = tid; idx < 128 * 32; idx += 256) {
            int row = idx >> 5, j = idx & 31;
            reinterpret_cast<float4*>(P + row * A_S)[j] = src[row * 32 + j];
        }
        for (int i = tid; i < 4096; i += 256)
            reinterpret_cast<float4*>(WB)[i] = reinterpret_cast<const float4*>(Wp)[i];
    }
    __syncthreads();

    float acc[8][8];

    gemm_tile_128(P, WB, acc, ty, tx);
    #pragma unroll
    for (int i = 0; i < 8; i++) {
        int r = ty * 8 + i;
        int t = r & 7;
        #pragma unroll
        for (int j = 0; j < 8; j++) {
            int c = tx * 8 + j;
            Q[r * A_S + c] = acc[i][j] + bp[c] + query[t * C + c];
        }
    }
    __syncthreads();

    {
        int warp = tid >> 5, lane = tid & 31;
        for (int r = warp; r < 128; r += 8) {
            float4 v = *reinterpret_cast<const float4*>(&Q[r * A_S + lane * 4]);
            float s = v.x + v.y + v.z + v.w;
            #pragma unroll
            for (int o = 16; o; o >>= 1) s += __shfl_xor_sync(0xffffffffu, s, o);
            float mean = s * (1.0f / 128.0f);
            float dx = v.x - mean, dy = v.y - mean, dz = v.z - mean, dw = v.w - mean;
            float sq = dx * dx + dy * dy + dz * dz + dw * dw;
            #pragma unroll
            for (int o = 16; o; o >>= 1) sq += __shfl_xor_sync(0xffffffffu, sq, o);
            float inv = rsqrtf(sq * (1.0f / 128.0f) + 1e-5f);
            int c = lane * 4;
            float4 gg = *reinterpret_cast<const float4*>(&g2[c]);
            float4 bb = *reinterpret_cast<const float4*>(&b2[c]);
            float4 o4;
            o4.x = dx * inv * gg.x + bb.x;
            o4.y = dy * inv * gg.y + bb.y;
            o4.z = dz * inv * gg.z + bb.z;
            o4.w = dw * inv * gg.w + bb.w;
            *reinterpret_cast<float4*>(&P[r * A_S + c]) = o4;
        }
        for (int i = tid; i < 4096; i += 256)
            reinterpret_cast<float4*>(WB)[i] = reinterpret_cast<const float4*>(Wf1)[i];
    }
    __syncthreads();

    gemm_tile_128(P, WB, acc, ty, tx);
    __syncthreads();
    #pragma unroll
    for (int i = 0; i < 8; i++) {
        int r = ty * 8 + i;
        #pragma unroll
        for (int j = 0; j < 8; j++) {
            int c = tx * 8 + j;
            float v = acc[i][j] + bf1[c];
            P[r * A_S + c] = 0.5f * v * (1.0f + erff(v * 0.70710678118654752f));
        }
    }
    for (int i = tid; i < 4096; i += 256)
        reinterpret_cast<float4*>(WB)[i] = reinterpret_cast<const float4*>(Wf2)[i];
    __syncthreads();

    gemm_tile_128(P, WB, acc, ty, tx);
    #pragma unroll
    for (int i = 0; i < 8; i++) {
        int r = ty * 8 + i;
        float* orow = out + (size_t)(R0 + r) * C;
        #pragma unroll
        for (int j = 0; j < 8; j++) {
            int c = tx * 8 + j;
            orow[c] = acc[i][j] + bf2[c] + Q[r * A_S + c];
        }
    }
}

// ---------------------------------------------------------------------------
extern "C" void kernel_launch(void* const* d_in, const int* in_sizes, int n_in,
                              void* d_out, int out_size) {
    const float* query = (const float*)d_in[0];
    const float* tgt   = (const float*)d_in[1];
    const float* ln1g  = (const float*)d_in[2];
    const float* ln1b  = (const float*)d_in[3];
    const float* ln2g  = (const float*)d_in[4];
    const float* ln2b  = (const float*)d_in[5];
    const float* Wq    = (const float*)d_in[6];
    const float* bq    = (const float*)d_in[7];
    const float* Wk    = (const float*)d_in[8];
    // d_in[9] = bk (cancels in softmax)
    const float* Wv    = (const float*)d_in[10];
    const float* bv    = (const float*)d_in[11];
    const float* Wp    = (const float*)d_in[12];
    const float* bp    = (const float*)d_in[13];
    const float* Wf1   = (const float*)d_in[14];
    const float* bf1   = (const float*)d_in[15];
    const float* Wf2   = (const float*)d_in[16];
    const float* bf2   = (const float*)d_in[17];

    int B = in_sizes[1] / (L * C);
    if (B > MAXB) B = MAXB;

    const int K1_SMEM = (64 * 128 + 128 * WVT_S + 128 + L * 128 + 64 * W_S + 8 * SP_S) * sizeof(float);
    const int K2_SMEM = (16384 + 2 * 128 * A_S) * sizeof(float);

    cudaFuncSetAttribute(attn_kernel, cudaFuncAttributeMaxDynamicSharedMemorySize, K1_SMEM);
    cudaFuncSetAttribute(ffn_kernel,  cudaFuncAttributeMaxDynamicSharedMemorySize, K2_SMEM);

    prep_kernel<<<64, 128>>>(query, ln1g, ln1b, Wq, bq, Wk);
    attn_kernel<<<(B + BPB - 1) / BPB, 512, K1_SMEM>>>(tgt, Wv, bv, B);

    int nrows = B * NTOK;
    ffn_kernel<<<(nrows + 127) / 128, 256, K2_SMEM>>>(query, ln2g, ln2b,
                                                      Wp, bp, Wf1, bf1, Wf2, bf2,
                                                      (float*)d_out, nrows);
}

// round 3
// speedup vs baseline: 2.1416x; 1.5631x over previous
#include <cuda_runtime.h>
#include <math.h>

// Problem constants
#define C 128
#define L 54            // 6*9
#define NTOK 8
#define MAXB 8192
#define BPB 8

// smem strides
#define W_S   132
#define WVT_S 132
#define SP_S  80
#define AS    132       // ffn operand stride
#define WS    132       // ffn weight stride

// Scratch
__device__ float g_qk[64 * 128];
__device__ float g_att[(size_t)MAXB * NTOK * C];

// ---------------------------------------------------------------------------
__device__ __forceinline__ unsigned smem_u32(const void* p) {
    unsigned a;
    asm("{ .reg .u64 t; cvta.to.shared.u64 t, %1; cvt.u32.u64 %0, t; }" : "=r"(a) : "l"(p));
    return a;
}

// ---------------------------------------------------------------------------
// K0: prep (unchanged)
// ---------------------------------------------------------------------------
__global__ void prep_kernel(const float* __restrict__ q_in,
                            const float* __restrict__ g1, const float* __restrict__ b1,
                            const float* __restrict__ Wq, const float* __restrict__ bq,
                            const float* __restrict__ Wk) {
    __shared__ float s_qn[128];
    __shared__ float s_qh[16];
    __shared__ float s_red[8];
    int th = blockIdx.x, t = th >> 3, h = th & 7;
    int tid = threadIdx.x, lane = tid & 31, warp = tid >> 5;

    float x = q_in[t * 128 + tid];
    float s = x;
    #pragma unroll
    for (int o = 16; o; o >>= 1) s += __shfl_xor_sync(~0u, s, o);
    if (lane == 0) s_red[warp] = s;
    __syncthreads();
    float mean = (s_red[0] + s_red[1] + s_red[2] + s_red[3]) * (1.0f / 128.0f);
    float dx = x - mean;
    float sq = dx * dx;
    #pragma unroll
    for (int o = 16; o; o >>= 1) sq += __shfl_xor_sync(~0u, sq, o);
    __syncthreads();
    if (lane == 0) s_red[warp] = sq;
    __syncthreads();
    float var = (s_red[0] + s_red[1] + s_red[2] + s_red[3]) * (1.0f / 128.0f);
    float inv = rsqrtf(var + 1e-5f);
    s_qn[tid] = dx * inv * g1[tid] + b1[tid];
    __syncthreads();

    int j = tid >> 3, seg = tid & 7;
    int o = h * 16 + j;
    float p = 0.0f;
    #pragma unroll
    for (int i = 0; i < 16; i++) p += s_qn[seg * 16 + i] * Wq[(seg * 16 + i) * 128 + o];
    #pragma unroll
    for (int off = 4; off; off >>= 1) p += __shfl_xor_sync(~0u, p, off);
    if (seg == 0) s_qh[j] = p + bq[o];
    __syncthreads();

    float acc = 0.0f;
    const float* wk = Wk + tid * 128 + h * 16;
    #pragma unroll
    for (int jj = 0; jj < 16; jj++) acc += s_qh[jj] * wk[jj];
    g_qk[th * 128 + tid] = acc * 0.25f;
}

// ---------------------------------------------------------------------------
// K1: fused attention + cp.async double-buffered tgt
// ---------------------------------------------------------------------------
__global__ __launch_bounds__(512, 1)
void attn_kernel(const float* __restrict__ tgt,
                 const float* __restrict__ Wv, const float* __restrict__ bv,
                 int B) {
    extern __shared__ float sm[];
    float* s_qk  = sm;                       //  8192
    float* s_wvT = s_qk  + 64 * 128;         // 16896
    float* s_bv  = s_wvT + 128 * WVT_S;      //   128
    float* s_tgt = s_bv  + 128;              //  2 * 6912
    float* s_w   = s_tgt + 2 * L * 128;      //  8448
    float* s_p   = s_w   + 64 * W_S;         //   640

    int tid = threadIdx.x;
    int warp = tid >> 5, lane = tid & 31;

    // prologue: async load of first batch's tgt
    {
        int b0 = blockIdx.x * BPB;
        if (b0 < B) {
            const float4* src = reinterpret_cast<const float4*>(tgt + (size_t)b0 * L * C);
            for (int idx = tid; idx < L * 32; idx += 512) {
                unsigned dst = smem_u32(s_tgt + idx * 4);
                asm volatile("cp.async.ca.shared.global [%0], [%1], 16;\n"
                             :: "r"(dst), "l"(src + idx));
            }
        }
        asm volatile("cp.async.commit_group;\n");
    }

    // stage qk, WvT, bv
    for (int idx = tid; idx < 2048; idx += 512)
        reinterpret_cast<float4*>(s_qk)[idx] = reinterpret_cast<const float4*>(g_qk)[idx];
    for (int idx = tid; idx < 16384; idx += 512) {
        int o = idx & 127, c = idx >> 7;
        s_wvT[o * WVT_S + c] = Wv[c * 128 + o];
    }
    if (tid < 128) s_bv[tid] = bv[tid];

    // role decomposition
    int t_tok = warp >> 1, half = warp & 1;
    int hq = lane >> 3, c8 = lane & 7;
    int hh = half * 4 + hq;
    int qrow = t_tok * 8 + hh;
    int r = (t_tok < 2) ? t_tok : (t_tok - 2);
    int base_l = (r / 3) * 27 + (r % 3) * 3;
    const int loff[9] = {0, 1, 2, 9, 10, 11, 18, 19, 20};

    int tpair = lane >> 3;
    int hB = warp >> 1;

    __syncthreads();   // staging done

    float4 qk4[4];
    #pragma unroll
    for (int jj = 0; jj < 4; jj++)
        qk4[jj] = *reinterpret_cast<const float4*>(s_qk + qrow * 128 + c8 * 4 + 32 * jj);

    for (int bi = 0; bi < BPB; bi++) {
        int b = blockIdx.x * BPB + bi;
        if (b >= B) break;

        float* cur = s_tgt + (bi & 1) * (L * 128);
        float* nxt = s_tgt + ((bi + 1) & 1) * (L * 128);

        // prefetch next batch (buffer nxt was last read in iteration bi-1, protected by its end sync)
        int nb = b + 1;
        if (bi + 1 < BPB && nb < B) {
            const float4* src = reinterpret_cast<const float4*>(tgt + (size_t)nb * L * C);
            for (int idx = tid; idx < L * 32; idx += 512) {
                unsigned dst = smem_u32(nxt + idx * 4);
                asm volatile("cp.async.ca.shared.global [%0], [%1], 16;\n"
                             :: "r"(dst), "l"(src + idx));
            }
        }
        asm volatile("cp.async.commit_group;\n");
        asm volatile("cp.async.wait_group 1;\n");
        __syncthreads();   // cur buffer visible to all

        // ---- dots ----
        float d[9];
        #pragma unroll
        for (int li = 0; li < 9; li++) {
            const float* row = cur + (base_l + loff[li]) * 128;
            float a = 0.0f;
            #pragma unroll
            for (int jj = 0; jj < 4; jj++) {
                float4 x4 = *reinterpret_cast<const float4*>(row + c8 * 4 + 32 * jj);
                a = fmaf(qk4[jj].x, x4.x, a);
                a = fmaf(qk4[jj].y, x4.y, a);
                a = fmaf(qk4[jj].z, x4.z, a);
                a = fmaf(qk4[jj].w, x4.w, a);
            }
            d[li] = a;
        }
        #pragma unroll
        for (int off = 4; off; off >>= 1) {
            #pragma unroll
            for (int li = 0; li < 9; li++)
                d[li] += __shfl_xor_sync(~0u, d[li], off);
        }
        if (c8 == 0) {
            #pragma unroll
            for (int li = 0; li < 9; li++)
                s_p[t_tok * SP_S + hh * 9 + li] = d[li];
        }
        __syncthreads();

        // ---- softmax ----
        if (tid < 64) {
            float* pp = s_p + (tid >> 3) * SP_S + (tid & 7) * 9;
            float m = -1e30f;
            #pragma unroll
            for (int li = 0; li < 9; li++) m = fmaxf(m, pp[li]);
            float e[9]; float ssum = 0.0f;
            #pragma unroll
            for (int li = 0; li < 9; li++) { e[li] = expf(pp[li] - m); ssum += e[li]; }
            float invs = 1.0f / ssum;
            #pragma unroll
            for (int li = 0; li < 9; li++) pp[li] = e[li] * invs;
        }
        __syncthreads();

        // ---- attention-weighted sum ----
        {
            float4 w4[4];
            #pragma unroll
            for (int jj = 0; jj < 4; jj++) w4[jj] = make_float4(0.f, 0.f, 0.f, 0.f);
            #pragma unroll
            for (int li = 0; li < 9; li++) {
                float a = s_p[t_tok * SP_S + hh * 9 + li];
                const float* row = cur + (base_l + loff[li]) * 128;
                #pragma unroll
                for (int jj = 0; jj < 4; jj++) {
                    float4 x4 = *reinterpret_cast<const float4*>(row + c8 * 4 + 32 * jj);
                    w4[jj].x = fmaf(a, x4.x, w4[jj].x);
                    w4[jj].y = fmaf(a, x4.y, w4[jj].y);
                    w4[jj].z = fmaf(a, x4.z, w4[jj].z);
                    w4[jj].w = fmaf(a, x4.w, w4[jj].w);
                }
            }
            #pragma unroll
            for (int jj = 0; jj < 4; jj++)
                *reinterpret_cast<float4*>(s_w + qrow * W_S + c8 * 4 + 32 * jj) = w4[jj];
        }
        __syncthreads();

        // ---- Wv contraction ----
        {
            float4 w4[2][4];
            #pragma unroll
            for (int tt = 0; tt < 2; tt++) {
                int t = tpair + tt * 4;
                const float* row = s_w + (t * 8 + hB) * W_S;
                #pragma unroll
                for (int jj = 0; jj < 4; jj++)
                    w4[tt][jj] = *reinterpret_cast<const float4*>(row + c8 * 4 + 32 * jj);
            }
            float acc[2][8];
            #pragma unroll
            for (int tt = 0; tt < 2; tt++)
                #pragma unroll
                for (int oo = 0; oo < 8; oo++) acc[tt][oo] = 0.0f;

            #pragma unroll
            for (int jj = 0; jj < 4; jj++) {
                #pragma unroll
                for (int oo = 0; oo < 8; oo++) {
                    float4 v4 = *reinterpret_cast<const float4*>(
                        s_wvT + (warp * 8 + oo) * WVT_S + c8 * 4 + 32 * jj);
                    #pragma unroll
                    for (int tt = 0; tt < 2; tt++) {
                        float aa = acc[tt][oo];
                        aa = fmaf(w4[tt][jj].x, v4.x, aa);
                        aa = fmaf(w4[tt][jj].y, v4.y, aa);
                        aa = fmaf(w4[tt][jj].z, v4.z, aa);
                        aa = fmaf(w4[tt][jj].w, v4.w, aa);
                        acc[tt][oo] = aa;
                    }
                }
            }
            #pragma unroll
            for (int off = 4; off; off >>= 1)
                #pragma unroll
                for (int tt = 0; tt < 2; tt++)
                    #pragma unroll
                    for (int oo = 0; oo < 8; oo++)
                        acc[tt][oo] += __shfl_xor_sync(~0u, acc[tt][oo], off);

            if (c8 == 0) {
                float4 bva = *reinterpret_cast<const float4*>(s_bv + warp * 8);
                float4 bvb = *reinterpret_cast<const float4*>(s_bv + warp * 8 + 4);
                #pragma unroll
                for (int tt = 0; tt < 2; tt++) {
                    int t = tpair + tt * 4;
                    float* op = g_att + ((size_t)b * NTOK + t) * C + warp * 8;
                    *reinterpret_cast<float4*>(op) =
                        make_float4(acc[tt][0] + bva.x, acc[tt][1] + bva.y,
                                    acc[tt][2] + bva.z, acc[tt][3] + bva.w);
                    *reinterpret_cast<float4*>(op + 4) =
                        make_float4(acc[tt][4] + bvb.x, acc[tt][5] + bvb.y,
                                    acc[tt][6] + bvb.z, acc[tt][7] + bvb.w);
                }
            }
        }
        __syncthreads();
    }
}

// ---------------------------------------------------------------------------
// K2: FFN chain via mma.sync tf32. 512 threads = 16 warps (4 M x 4 N).
// ---------------------------------------------------------------------------
__device__ __forceinline__ void mma_tf32(float* acc, unsigned a0, unsigned a1,
                                         unsigned a2, unsigned a3,
                                         unsigned b0, unsigned b1) {
    asm volatile(
        "mma.sync.aligned.m16n8k8.row.col.f32.tf32.tf32.f32 "
        "{%0,%1,%2,%3},{%4,%5,%6,%7},{%8,%9},{%0,%1,%2,%3};\n"
        : "+f"(acc[0]), "+f"(acc[1]), "+f"(acc[2]), "+f"(acc[3])
        : "r"(a0), "r"(a1), "r"(a2), "r"(a3), "r"(b0), "r"(b1));
}

// One 128x128x128 GEMM: acc[mt][nt][4], warp covers 32 rows x 32 cols.
__device__ __forceinline__ void gemm_mma(const float* __restrict__ P,
                                         const float* __restrict__ WB,
                                         float acc[2][4][4], int RM, int CN, int lane) {
    #pragma unroll
    for (int mt = 0; mt < 2; mt++)
        #pragma unroll
        for (int nt = 0; nt < 4; nt++)
            #pragma unroll
            for (int i = 0; i < 4; i++) acc[mt][nt][i] = 0.0f;

    const unsigned* Pu = reinterpret_cast<const unsigned*>(P);
    const unsigned* Wu = reinterpret_cast<const unsigned*>(WB);
    int g = lane >> 2, t = lane & 3;

    #pragma unroll
    for (int k0 = 0; k0 < 128; k0 += 8) {
        int kr = k0 + t;
        unsigned a[2][4];
        #pragma unroll
        for (int mt = 0; mt < 2; mt++) {
            int r0 = RM + mt * 16 + g;
            a[mt][0] = Pu[r0 * AS + kr];
            a[mt][1] = Pu[(r0 + 8) * AS + kr];
            a[mt][2] = Pu[r0 * AS + kr + 4];
            a[mt][3] = Pu[(r0 + 8) * AS + kr + 4];
        }
        unsigned bfr[4][2];
        #pragma unroll
        for (int nt = 0; nt < 4; nt++) {
            int c0 = CN + nt * 8 + g;
            bfr[nt][0] = Wu[kr * WS + c0];
            bfr[nt][1] = Wu[(kr + 4) * WS + c0];
        }
        #pragma unroll
        for (int mt = 0; mt < 2; mt++)
            #pragma unroll
            for (int nt = 0; nt < 4; nt++)
                mma_tf32(acc[mt][nt], a[mt][0], a[mt][1], a[mt][2], a[mt][3],
                         bfr[nt][0], bfr[nt][1]);
    }
}

__global__ __launch_bounds__(512, 1)
void ffn_kernel(const float* __restrict__ query,
                const float* __restrict__ g2, const float* __restrict__ b2,
                const float* __restrict__ Wp, const float* __restrict__ bp,
                const float* __restrict__ Wf1, const float* __restrict__ bf1,
                const float* __restrict__ Wf2, const float* __restrict__ bf2,
                float* __restrict__ out, int nrows) {
    extern __shared__ float sm[];
    float* WB  = sm;                    // 128*WS
    float* P   = WB + 128 * WS;         // 128*AS
    float* Q   = P  + 128 * AS;         // 128*AS
    float* s_qr  = Q + 128 * AS;        // 1024
    float* s_bp  = s_qr + 1024;         // 128
    float* s_bf1 = s_bp + 128;          // 128
    float* s_bf2 = s_bf1 + 128;         // 128
    float* s_g2  = s_bf2 + 128;         // 128
    float* s_b2  = s_g2 + 128;          // 128

    int tid = threadIdx.x;
    int warp = tid >> 5, lane = tid & 31;
    int g = lane >> 2, t4 = lane & 3;
    int RM = (warp >> 2) * 32, CN = (warp & 3) * 32;
    int R0 = blockIdx.x * 128;
    if (R0 >= nrows) return;

    // stage: P = att tile, WB = Wp, misc
    {
        const float4* src = reinterpret_cast<const float4*>(g_att + (size_t)R0 * C);
        for (int idx = tid; idx < 128 * 32; idx += 512) {
            int row = idx >> 5, j = idx & 31;
            reinterpret_cast<float4*>(P + row * AS)[j] = src[row * 32 + j];
        }
        for (int idx = tid; idx < 128 * 32; idx += 512) {
            int row = idx >> 5, j = idx & 31;
            reinterpret_cast<float4*>(WB + row * WS)[j] =
                reinterpret_cast<const float4*>(Wp)[row * 32 + j];
        }
        for (int i = tid; i < 1024; i += 512) s_qr[i] = query[i];
        if (tid < 128) {
            s_bp[tid] = bp[tid]; s_bf1[tid] = bf1[tid]; s_bf2[tid] = bf2[tid];
            s_g2[tid] = g2[tid]; s_b2[tid] = b2[tid];
        }
    }
    __syncthreads();

    float acc[2][4][4];

    // ---- GEMM1: X = att@Wp + bp + shortcut -> Q ----
    gemm_mma(P, WB, acc, RM, CN, lane);
    #pragma unroll
    for (int mt = 0; mt < 2; mt++) {
        int r = RM + mt * 16 + g;
        #pragma unroll
        for (int nt = 0; nt < 4; nt++) {
            int c = CN + nt * 8 + 2 * t4;
            int tq = r & 7;
            *reinterpret_cast<float2*>(&Q[r * AS + c]) = make_float2(
                acc[mt][nt][0] + s_bp[c]     + s_qr[tq * 128 + c],
                acc[mt][nt][1] + s_bp[c + 1] + s_qr[tq * 128 + c + 1]);
            *reinterpret_cast<float2*>(&Q[(r + 8) * AS + c]) = make_float2(
                acc[mt][nt][2] + s_bp[c]     + s_qr[tq * 128 + c],
                acc[mt][nt][3] + s_bp[c + 1] + s_qr[tq * 128 + c + 1]);
        }
    }
    __syncthreads();   // Q complete, WB/P reads done

    // ---- LN rows Q -> P ; load Wf1 -> WB ----
    {
        for (int r = warp; r < 128; r += 16) {
            float4 v = *reinterpret_cast<const float4*>(&Q[r * AS + lane * 4]);
            float s = v.x + v.y + v.z + v.w;
            #pragma unroll
            for (int o = 16; o; o >>= 1) s += __shfl_xor_sync(~0u, s, o);
            float mean = s * (1.0f / 128.0f);
            float dx = v.x - mean, dy = v.y - mean, dz = v.z - mean, dw = v.w - mean;
            float sq = dx * dx + dy * dy + dz * dz + dw * dw;
            #pragma unroll
            for (int o = 16; o; o >>= 1) sq += __shfl_xor_sync(~0u, sq, o);
            float inv = rsqrtf(sq * (1.0f / 128.0f) + 1e-5f);
            int c = lane * 4;
            float4 gg = *reinterpret_cast<const float4*>(&s_g2[c]);
            float4 bb = *reinterpret_cast<const float4*>(&s_b2[c]);
            float4 o4;
            o4.x = dx * inv * gg.x + bb.x;
            o4.y = dy * inv * gg.y + bb.y;
            o4.z = dz * inv * gg.z + bb.z;
            o4.w = dw * inv * gg.w + bb.w;
            *reinterpret_cast<float4*>(&P[r * AS + c]) = o4;
        }
        for (int idx = tid; idx < 128 * 32; idx += 512) {
            int row = idx >> 5, j = idx & 31;
            reinterpret_cast<float4*>(WB + row * WS)[j] =
                reinterpret_cast<const float4*>(Wf1)[row * 32 + j];
        }
    }
    __syncthreads();

    // ---- GEMM2: H1 = gelu(Xn@Wf1 + bf1) -> P ----
    gemm_mma(P, WB, acc, RM, CN, lane);
    __syncthreads();   // all reads of P/WB done before overwrite
    #pragma unroll
    for (int mt = 0; mt < 2; mt++) {
        int r = RM + mt * 16 + g;
        #pragma unroll
        for (int nt = 0; nt < 4; nt++) {
            int c = CN + nt * 8 + 2 * t4;
            float v0 = acc[mt][nt][0] + s_bf1[c];
            float v1 = acc[mt][nt][1] + s_bf1[c + 1];
            float v2 = acc[mt][nt][2] + s_bf1[c];
            float v3 = acc[mt][nt][3] + s_bf1[c + 1];
            const float k = 0.70710678118654752f;
            *reinterpret_cast<float2*>(&P[r * AS + c]) = make_float2(
                0.5f * v0 * (1.0f + erff(v0 * k)),
                0.5f * v1 * (1.0f + erff(v1 * k)));
            *reinterpret_cast<float2*>(&P[(r + 8) * AS + c]) = make_float2(
                0.5f * v2 * (1.0f + erff(v2 * k)),
                0.5f * v3 * (1.0f + erff(v3 * k)));
        }
    }
    for (int idx = tid; idx < 128 * 32; idx += 512) {
        int row = idx >> 5, j = idx & 31;
        reinterpret_cast<float4*>(WB + row * WS)[j] =
            reinterpret_cast<const float4*>(Wf2)[row * 32 + j];
    }
    __syncthreads();

    // ---- GEMM3: out = X + H1@Wf2 + bf2 ----
    gemm_mma(P, WB, acc, RM, CN, lane);
    #pragma unroll
    for (int mt = 0; mt < 2; mt++) {
        int r = RM + mt * 16 + g;
        #pragma unroll
        for (int nt = 0; nt < 4; nt++) {
            int c = CN + nt * 8 + 2 * t4;
            float2 q0 = *reinterpret_cast<const float2*>(&Q[r * AS + c]);
            float2 q1 = *reinterpret_cast<const float2*>(&Q[(r + 8) * AS + c]);
            float* o0 = out + (size_t)(R0 + r) * C + c;
            float* o1 = out + (size_t)(R0 + r + 8) * C + c;
            *reinterpret_cast<float2*>(o0) = make_float2(
                acc[mt][nt][0] + s_bf2[c] + q0.x,
                acc[mt][nt][1] + s_bf2[c + 1] + q0.y);
            *reinterpret_cast<float2*>(o1) = make_float2(
                acc[mt][nt][2] + s_bf2[c] + q1.x,
                acc[mt][nt][3] + s_bf2[c + 1] + q1.y);
        }
    }
}

// ---------------------------------------------------------------------------
extern "C" void kernel_launch(void* const* d_in, const int* in_sizes, int n_in,
                              void* d_out, int out_size) {
    const float* query = (const float*)d_in[0];
    const float* tgt   = (const float*)d_in[1];
    const float* ln1g  = (const float*)d_in[2];
    const float* ln1b  = (const float*)d_in[3];
    const float* ln2g  = (const float*)d_in[4];
    const float* ln2b  = (const float*)d_in[5];
    const float* Wq    = (const float*)d_in[6];
    const float* bq    = (const float*)d_in[7];
    const float* Wk    = (const float*)d_in[8];
    // d_in[9] = bk (cancels in softmax)
    const float* Wv    = (const float*)d_in[10];
    const float* bv    = (const float*)d_in[11];
    const float* Wp    = (const float*)d_in[12];
    const float* bp    = (const float*)d_in[13];
    const float* Wf1   = (const float*)d_in[14];
    const float* bf1   = (const float*)d_in[15];
    const float* Wf2   = (const float*)d_in[16];
    const float* bf2   = (const float*)d_in[17];

    int B = in_sizes[1] / (L * C);
    if (B > MAXB) B = MAXB;

    const int K1_SMEM = (64 * 128 + 128 * WVT_S + 128 + 2 * L * 128 + 64 * W_S + 8 * SP_S)
                        * sizeof(float);
    const int K2_SMEM = (128 * WS + 2 * 128 * AS + 1024 + 5 * 128) * sizeof(float);

    cudaFuncSetAttribute(attn_kernel, cudaFuncAttributeMaxDynamicSharedMemorySize, K1_SMEM);
    cudaFuncSetAttribute(ffn_kernel,  cudaFuncAttributeMaxDynamicSharedMemorySize, K2_SMEM);

    prep_kernel<<<64, 128>>>(query, ln1g, ln1b, Wq, bq, Wk);
    attn_kernel<<<(B + BPB - 1) / BPB, 512, K1_SMEM>>>(tgt, Wv, bv, B);

    int nrows = B * NTOK;
    ffn_kernel<<<(nrows + 127) / 128, 512, K2_SMEM>>>(query, ln2g, ln2b,
                                                      Wp, bp, Wf1, bf1, Wf2, bf2,
                                                      (float*)d_out, nrows);
}

// round 4
// speedup vs baseline: 2.4741x; 1.1553x over previous
#include <cuda_runtime.h>
#include <math.h>

// Problem constants
#define C 128
#define L 54            // 6*9
#define NTOK 8
#define MAXB 8192
#define BPB 8

// attn smem strides (floats)
#define TS   132        // s_tgt row stride
#define QS   132        // s_qkp row stride
#define WSM  132        // s_w row stride
#define SPS  20         // s_p (probs) row stride
#define WVS  132        // s_wv row stride

// ffn strides
#define AS   132
#define WS   132

// Scratch
__device__ float g_qk[64 * 128];
__device__ float g_att[(size_t)MAXB * NTOK * C];

// ---------------------------------------------------------------------------
__device__ __forceinline__ unsigned smem_u32(const void* p) {
    unsigned a;
    asm("{ .reg .u64 t; cvta.to.shared.u64 t, %1; cvt.u32.u64 %0, t; }" : "=r"(a) : "l"(p));
    return a;
}

__device__ __forceinline__ void mma_tf32(float* acc, unsigned a0, unsigned a1,
                                         unsigned a2, unsigned a3,
                                         unsigned b0, unsigned b1) {
    asm volatile(
        "mma.sync.aligned.m16n8k8.row.col.f32.tf32.tf32.f32 "
        "{%0,%1,%2,%3},{%4,%5,%6,%7},{%8,%9},{%0,%1,%2,%3};\n"
        : "+f"(acc[0]), "+f"(acc[1]), "+f"(acc[2]), "+f"(acc[3])
        : "r"(a0), "r"(a1), "r"(a2), "r"(a3), "r"(b0), "r"(b1));
}

__device__ __forceinline__ unsigned f2u(float x) { return __float_as_uint(x); }

// ---------------------------------------------------------------------------
// K0: prep (unchanged)
// ---------------------------------------------------------------------------
__global__ void prep_kernel(const float* __restrict__ q_in,
                            const float* __restrict__ g1, const float* __restrict__ b1,
                            const float* __restrict__ Wq, const float* __restrict__ bq,
                            const float* __restrict__ Wk) {
    __shared__ float s_qn[128];
    __shared__ float s_qh[16];
    __shared__ float s_red[8];
    int th = blockIdx.x, t = th >> 3, h = th & 7;
    int tid = threadIdx.x, lane = tid & 31, warp = tid >> 5;

    float x = q_in[t * 128 + tid];
    float s = x;
    #pragma unroll
    for (int o = 16; o; o >>= 1) s += __shfl_xor_sync(~0u, s, o);
    if (lane == 0) s_red[warp] = s;
    __syncthreads();
    float mean = (s_red[0] + s_red[1] + s_red[2] + s_red[3]) * (1.0f / 128.0f);
    float dx = x - mean;
    float sq = dx * dx;
    #pragma unroll
    for (int o = 16; o; o >>= 1) sq += __shfl_xor_sync(~0u, sq, o);
    __syncthreads();
    if (lane == 0) s_red[warp] = sq;
    __syncthreads();
    float var = (s_red[0] + s_red[1] + s_red[2] + s_red[3]) * (1.0f / 128.0f);
    float inv = rsqrtf(var + 1e-5f);
    s_qn[tid] = dx * inv * g1[tid] + b1[tid];
    __syncthreads();

    int j = tid >> 3, seg = tid & 7;
    int o = h * 16 + j;
    float p = 0.0f;
    #pragma unroll
    for (int i = 0; i < 16; i++) p += s_qn[seg * 16 + i] * Wq[(seg * 16 + i) * 128 + o];
    #pragma unroll
    for (int off = 4; off; off >>= 1) p += __shfl_xor_sync(~0u, p, off);
    if (seg == 0) s_qh[j] = p + bq[o];
    __syncthreads();

    float acc = 0.0f;
    const float* wk = Wk + tid * 128 + h * 16;
    #pragma unroll
    for (int jj = 0; jj < 16; jj++) acc += s_qh[jj] * wk[jj];
    g_qk[th * 128 + tid] = acc * 0.25f;
}

// ---------------------------------------------------------------------------
// region-row offset within region for li (0..8); li>=9 -> 0 (padding)
__device__ __forceinline__ int loff(int li) {
    if (li >= 9) return 0;
    int a = li / 3, b = li - a * 3;
    return a * 9 + b;
}

// ---------------------------------------------------------------------------
// K1: fused attention, all contractions via tf32 mma. 512 threads.
// Row layout:
//   s_qkp / s_p: region-major permuted rows prow = pos(t)*8 + h,
//     pos = t with 1<->2 swapped. Region tiles: bases {0,16,32,40,48,56}.
//   s_w: head-major rows vrow = h*8 + t.
// ---------------------------------------------------------------------------
__global__ __launch_bounds__(512, 1)
void attn_kernel(const float* __restrict__ tgt,
                 const float* __restrict__ Wv, const float* __restrict__ bv,
                 int B) {
    extern __shared__ float sm[];
    float* s_qkp = sm;                    // 80*132
    float* s_wv  = s_qkp + 80 * QS;       // 128*132
    float* s_bv  = s_wv  + 128 * WVS;     // 128
    float* s_tgt = s_bv  + 128;           // 2 * 54*132
    float* s_w   = s_tgt + 2 * L * TS;    // 80*132
    float* s_p   = s_w   + 80 * WSM;      // 80*20

    int tid = threadIdx.x;
    int warp = tid >> 5, lane = tid & 31;
    int g = lane >> 2, t4 = lane & 3;

    // prologue: cp.async first batch into buffer 0
    {
        int b0 = blockIdx.x * BPB;
        if (b0 < B) {
            const float4* src = reinterpret_cast<const float4*>(tgt + (size_t)b0 * L * C);
            for (int idx = tid; idx < L * 32; idx += 512) {
                int row = idx >> 5, j = idx & 31;
                unsigned dst = smem_u32(s_tgt + row * TS + j * 4);
                asm volatile("cp.async.ca.shared.global [%0], [%1], 16;\n"
                             :: "r"(dst), "l"(src + idx));
            }
        }
        asm volatile("cp.async.commit_group;\n");
    }

    // stage qk permuted (region-major rows)
    for (int idx = tid; idx < 64 * 128; idx += 512) {
        int tr = idx >> 7, c = idx & 127;
        int t = tr >> 3, h = tr & 7;
        int pos = t + (t == 1) - (t == 2);
        s_qkp[(pos * 8 + h) * QS + c] = g_qk[idx];
    }
    for (int i = 64 * QS + tid; i < 80 * QS; i += 512) s_qkp[i] = 0.0f;
    for (int i = tid; i < 80 * SPS; i += 512) s_p[i] = 0.0f;
    for (int idx = tid; idx < 16384; idx += 512) {
        int c = idx >> 7, o = idx & 127;
        s_wv[c * WVS + o] = Wv[idx];
    }
    if (tid < 128) s_bv[tid] = bv[tid];

    // ---- per-warp job parameters (static across batches) ----
    // D/W phases: 12 jobs = (region r, half nh)
    bool okD = warp < 12;
    int rD  = warp >> 1, nhD = warp & 1;
    int mbD = (rD < 2) ? rD * 16 : 32 + (rD - 2) * 8;
    int blD = (rD / 3) * 27 + (rD % 3) * 3;
    // D: lane's B row (n index = li)
    int liD = nhD * 8 + g;
    int lD  = blD + loff(liD);
    // W: B rows per k-position
    int lW0 = blD + loff(t4);
    int lW1 = blD + loff(t4 + 4);
    int lW2 = blD + loff(t4 + 8);
    int lW3 = blD + loff(t4 + 12);
    // V phase: 16 jobs = (head hV, half nhV)
    int hV = warp >> 1, nhV = warp & 1;
    int o0 = hV * 16 + nhV * 8;

    __syncthreads();

    for (int bi = 0; bi < BPB; bi++) {
        int b = blockIdx.x * BPB + bi;
        if (b >= B) break;

        float* cur = s_tgt + (bi & 1) * (L * TS);
        float* nxt = s_tgt + ((bi + 1) & 1) * (L * TS);

        int nb = b + 1;
        if (bi + 1 < BPB && nb < B) {
            const float4* src = reinterpret_cast<const float4*>(tgt + (size_t)nb * L * C);
            for (int idx = tid; idx < L * 32; idx += 512) {
                int row = idx >> 5, j = idx & 31;
                unsigned dst = smem_u32(nxt + row * TS + j * 4);
                asm volatile("cp.async.ca.shared.global [%0], [%1], 16;\n"
                             :: "r"(dst), "l"(src + idx));
            }
        }
        asm volatile("cp.async.commit_group;\n");
        asm volatile("cp.async.wait_group 1;\n");
        __syncthreads();

        // ---- D: dots via mma. C[m][n] = qk_m . tgt_{l_n} ----
        if (okD) {
            float acc[4] = {0.f, 0.f, 0.f, 0.f};
            const float* Brow = cur + lD * TS;
            const float* Arow0 = s_qkp + (mbD + g) * QS;
            const float* Arow1 = s_qkp + (mbD + g + 8) * QS;
            #pragma unroll
            for (int k0 = 0; k0 < 128; k0 += 8) {
                int kr = k0 + t4;
                mma_tf32(acc,
                         f2u(Arow0[kr]), f2u(Arow1[kr]),
                         f2u(Arow0[kr + 4]), f2u(Arow1[kr + 4]),
                         f2u(Brow[kr]), f2u(Brow[kr + 4]));
            }
            int li0 = nhD * 8 + 2 * t4;
            if (li0 < 8) {          // both cols valid
                *reinterpret_cast<float2*>(&s_p[(mbD + g) * SPS + li0]) =
                    make_float2(acc[0], acc[1]);
                if (rD < 2)
                    *reinterpret_cast<float2*>(&s_p[(mbD + g + 8) * SPS + li0]) =
                        make_float2(acc[2], acc[3]);
            } else if (li0 == 8) {  // only col 8 valid
                s_p[(mbD + g) * SPS + 8] = acc[0];
                if (rD < 2) s_p[(mbD + g + 8) * SPS + 8] = acc[2];
            }
        }
        __syncthreads();

        // ---- softmax over 9 per row (64 rows) ----
        if (tid < 64) {
            float* pp = s_p + tid * SPS;
            float m = -1e30f;
            #pragma unroll
            for (int li = 0; li < 9; li++) m = fmaxf(m, pp[li]);
            float e[9]; float ssum = 0.0f;
            #pragma unroll
            for (int li = 0; li < 9; li++) { e[li] = expf(pp[li] - m); ssum += e[li]; }
            float invs = 1.0f / ssum;
            #pragma unroll
            for (int li = 0; li < 9; li++) pp[li] = e[li] * invs;
        }
        __syncthreads();

        // ---- W: weighted sum via mma. C[m][c] = sum_li P[m][li] tgt[l_li][c] ----
        if (okD) {
            const float* Ar0 = s_p + (mbD + g) * SPS;
            const float* Ar1 = s_p + (mbD + g + 8) * SPS;
            unsigned a0 = f2u(Ar0[t4]),      a1 = f2u(Ar1[t4]);
            unsigned a2 = f2u(Ar0[t4 + 4]),  a3 = f2u(Ar1[t4 + 4]);
            unsigned a4 = f2u(Ar0[t4 + 8]),  a5 = f2u(Ar1[t4 + 8]);
            unsigned a6 = f2u(Ar0[t4 + 12]), a7 = f2u(Ar1[t4 + 12]);
            // output row mapping (prow -> vrow)
            int p0 = mbD + g;
            int pos0 = p0 >> 3;
            int t0 = pos0 + (pos0 == 1) - (pos0 == 2);
            int v0 = (p0 & 7) * 8 + t0;
            int p1 = mbD + g + 8;
            int pos1 = p1 >> 3;
            int t1 = pos1 + (pos1 == 1) - (pos1 == 2);
            int v1 = (p1 & 7) * 8 + t1;

            #pragma unroll
            for (int nt = 0; nt < 8; nt++) {
                int c0 = nhD * 64 + nt * 8;
                float acc[4] = {0.f, 0.f, 0.f, 0.f};
                mma_tf32(acc, a0, a1, a2, a3,
                         f2u(cur[lW0 * TS + c0 + g]), f2u(cur[lW1 * TS + c0 + g]));
                mma_tf32(acc, a4, a5, a6, a7,
                         f2u(cur[lW2 * TS + c0 + g]), f2u(cur[lW3 * TS + c0 + g]));
                int cc = c0 + 2 * t4;
                *reinterpret_cast<float2*>(&s_w[v0 * WSM + cc]) = make_float2(acc[0], acc[1]);
                if (rD < 2)
                    *reinterpret_cast<float2*>(&s_w[v1 * WSM + cc]) = make_float2(acc[2], acc[3]);
            }
        }
        __syncthreads();

        // ---- V: att[t, o] = w[vrow=hV*8+t] . Wv[:, o] + bv ----
        {
            float acc[4] = {0.f, 0.f, 0.f, 0.f};
            const float* Ar0 = s_w + (hV * 8 + g) * WSM;
            const float* Ar1 = s_w + (hV * 8 + g + 8) * WSM;
            #pragma unroll
            for (int k0 = 0; k0 < 128; k0 += 8) {
                int kr = k0 + t4;
                mma_tf32(acc,
                         f2u(Ar0[kr]), f2u(Ar1[kr]),
                         f2u(Ar0[kr + 4]), f2u(Ar1[kr + 4]),
                         f2u(s_wv[kr * WVS + o0 + g]),
                         f2u(s_wv[(kr + 4) * WVS + o0 + g]));
            }
            int o = o0 + 2 * t4;
            float* op = g_att + ((size_t)b * NTOK + g) * C + o;
            *reinterpret_cast<float2*>(op) =
                make_float2(acc[0] + s_bv[o], acc[1] + s_bv[o + 1]);
        }
        __syncthreads();
    }
}

// ---------------------------------------------------------------------------
// K2: FFN chain via mma.sync tf32 (unchanged from round 3)
// ---------------------------------------------------------------------------
__device__ __forceinline__ void gemm_mma(const float* __restrict__ P,
                                         const float* __restrict__ WB,
                                         float acc[2][4][4], int RM, int CN, int lane) {
    #pragma unroll
    for (int mt = 0; mt < 2; mt++)
        #pragma unroll
        for (int nt = 0; nt < 4; nt++)
            #pragma unroll
            for (int i = 0; i < 4; i++) acc[mt][nt][i] = 0.0f;

    const unsigned* Pu = reinterpret_cast<const unsigned*>(P);
    const unsigned* Wu = reinterpret_cast<const unsigned*>(WB);
    int g = lane >> 2, t = lane & 3;

    #pragma unroll
    for (int k0 = 0; k0 < 128; k0 += 8) {
        int kr = k0 + t;
        unsigned a[2][4];
        #pragma unroll
        for (int mt = 0; mt < 2; mt++) {
            int r0 = RM + mt * 16 + g;
            a[mt][0] = Pu[r0 * AS + kr];
            a[mt][1] = Pu[(r0 + 8) * AS + kr];
            a[mt][2] = Pu[r0 * AS + kr + 4];
            a[mt][3] = Pu[(r0 + 8) * AS + kr + 4];
        }
        unsigned bfr[4][2];
        #pragma unroll
        for (int nt = 0; nt < 4; nt++) {
            int c0 = CN + nt * 8 + g;
            bfr[nt][0] = Wu[kr * WS + c0];
            bfr[nt][1] = Wu[(kr + 4) * WS + c0];
        }
        #pragma unroll
        for (int mt = 0; mt < 2; mt++)
            #pragma unroll
            for (int nt = 0; nt < 4; nt++)
                mma_tf32(acc[mt][nt], a[mt][0], a[mt][1], a[mt][2], a[mt][3],
                         bfr[nt][0], bfr[nt][1]);
    }
}

__global__ __launch_bounds__(512, 1)
void ffn_kernel(const float* __restrict__ query,
                const float* __restrict__ g2, const float* __restrict__ b2,
                const float* __restrict__ Wp, const float* __restrict__ bp,
                const float* __restrict__ Wf1, const float* __restrict__ bf1,
                const float* __restrict__ Wf2, const float* __restrict__ bf2,
                float* __restrict__ out, int nrows) {
    extern __shared__ float sm[];
    float* WB  = sm;
    float* P   = WB + 128 * WS;
    float* Q   = P  + 128 * AS;
    float* s_qr  = Q + 128 * AS;
    float* s_bp  = s_qr + 1024;
    float* s_bf1 = s_bp + 128;
    float* s_bf2 = s_bf1 + 128;
    float* s_g2  = s_bf2 + 128;
    float* s_b2  = s_g2 + 128;

    int tid = threadIdx.x;
    int warp = tid >> 5, lane = tid & 31;
    int g = lane >> 2, t4 = lane & 3;
    int RM = (warp >> 2) * 32, CN = (warp & 3) * 32;
    int R0 = blockIdx.x * 128;
    if (R0 >= nrows) return;

    {
        const float4* src = reinterpret_cast<const float4*>(g_att + (size_t)R0 * C);
        for (int idx = tid; idx < 128 * 32; idx += 512) {
            int row = idx >> 5, j = idx & 31;
            reinterpret_cast<float4*>(P + row * AS)[j] = src[row * 32 + j];
        }
        for (int idx = tid; idx < 128 * 32; idx += 512) {
            int row = idx >> 5, j = idx & 31;
            reinterpret_cast<float4*>(WB + row * WS)[j] =
                reinterpret_cast<const float4*>(Wp)[row * 32 + j];
        }
        for (int i = tid; i < 1024; i += 512) s_qr[i] = query[i];
        if (tid < 128) {
            s_bp[tid] = bp[tid]; s_bf1[tid] = bf1[tid]; s_bf2[tid] = bf2[tid];
            s_g2[tid] = g2[tid]; s_b2[tid] = b2[tid];
        }
    }
    __syncthreads();

    float acc[2][4][4];

    gemm_mma(P, WB, acc, RM, CN, lane);
    #pragma unroll
    for (int mt = 0; mt < 2; mt++) {
        int r = RM + mt * 16 + g;
        #pragma unroll
        for (int nt = 0; nt < 4; nt++) {
            int c = CN + nt * 8 + 2 * t4;
            int tq = r & 7;
            *reinterpret_cast<float2*>(&Q[r * AS + c]) = make_float2(
                acc[mt][nt][0] + s_bp[c]     + s_qr[tq * 128 + c],
                acc[mt][nt][1] + s_bp[c + 1] + s_qr[tq * 128 + c + 1]);
            *reinterpret_cast<float2*>(&Q[(r + 8) * AS + c]) = make_float2(
                acc[mt][nt][2] + s_bp[c]     + s_qr[tq * 128 + c],
                acc[mt][nt][3] + s_bp[c + 1] + s_qr[tq * 128 + c + 1]);
        }
    }
    __syncthreads();

    {
        for (int r = warp; r < 128; r += 16) {
            float4 v = *reinterpret_cast<const float4*>(&Q[r * AS + lane * 4]);
            float s = v.x + v.y + v.z + v.w;
            #pragma unroll
            for (int o = 16; o; o >>= 1) s += __shfl_xor_sync(~0u, s, o);
            float mean = s * (1.0f / 128.0f);
            float dx = v.x - mean, dy = v.y - mean, dz = v.z - mean, dw = v.w - mean;
            float sq = dx * dx + dy * dy + dz * dz + dw * dw;
            #pragma unroll
            for (int o = 16; o; o >>= 1) sq += __shfl_xor_sync(~0u, sq, o);
            float inv = rsqrtf(sq * (1.0f / 128.0f) + 1e-5f);
            int c = lane * 4;
            float4 gg = *reinterpret_cast<const float4*>(&s_g2[c]);
            float4 bb = *reinterpret_cast<const float4*>(&s_b2[c]);
            float4 o4;
            o4.x = dx * inv * gg.x + bb.x;
            o4.y = dy * inv * gg.y + bb.y;
            o4.z = dz * inv * gg.z + bb.z;
            o4.w = dw * inv * gg.w + bb.w;
            *reinterpret_cast<float4*>(&P[r * AS + c]) = o4;
        }
        for (int idx = tid; idx < 128 * 32; idx += 512) {
            int row = idx >> 5, j = idx & 31;
            reinterpret_cast<float4*>(WB + row * WS)[j] =
                reinterpret_cast<const float4*>(Wf1)[row * 32 + j];
        }
    }
    __syncthreads();

    gemm_mma(P, WB, acc, RM, CN, lane);
    __syncthreads();
    #pragma unroll
    for (int mt = 0; mt < 2; mt++) {
        int r = RM + mt * 16 + g;
        #pragma unroll
        for (int nt = 0; nt < 4; nt++) {
            int c = CN + nt * 8 + 2 * t4;
            float v0 = acc[mt][nt][0] + s_bf1[c];
            float v1 = acc[mt][nt][1] + s_bf1[c + 1];
            float v2 = acc[mt][nt][2] + s_bf1[c];
            float v3 = acc[mt][nt][3] + s_bf1[c + 1];
            const float k = 0.70710678118654752f;
            *reinterpret_cast<float2*>(&P[r * AS + c]) = make_float2(
                0.5f * v0 * (1.0f + erff(v0 * k)),
                0.5f * v1 * (1.0f + erff(v1 * k)));
            *reinterpret_cast<float2*>(&P[(r + 8) * AS + c]) = make_float2(
                0.5f * v2 * (1.0f + erff(v2 * k)),
                0.5f * v3 * (1.0f + erff(v3 * k)));
        }
    }
    for (int idx = tid; idx < 128 * 32; idx += 512) {
        int row = idx >> 5, j = idx & 31;
        reinterpret_cast<float4*>(WB + row * WS)[j] =
            reinterpret_cast<const float4*>(Wf2)[row * 32 + j];
    }
    __syncthreads();

    gemm_mma(P, WB, acc, RM, CN, lane);
    #pragma unroll
    for (int mt = 0; mt < 2; mt++) {
        int r = RM + mt * 16 + g;
        #pragma unroll
        for (int nt = 0; nt < 4; nt++) {
            int c = CN + nt * 8 + 2 * t4;
            float2 q0 = *reinterpret_cast<const float2*>(&Q[r * AS + c]);
            float2 q1 = *reinterpret_cast<const float2*>(&Q[(r + 8) * AS + c]);
            float* o0 = out + (size_t)(R0 + r) * C + c;
            float* o1 = out + (size_t)(R0 + r + 8) * C + c;
            *reinterpret_cast<float2*>(o0) = make_float2(
                acc[mt][nt][0] + s_bf2[c] + q0.x,
                acc[mt][nt][1] + s_bf2[c + 1] + q0.y);
            *reinterpret_cast<float2*>(o1) = make_float2(
                acc[mt][nt][2] + s_bf2[c] + q1.x,
                acc[mt][nt][3] + s_bf2[c + 1] + q1.y);
        }
    }
}

// ---------------------------------------------------------------------------
extern "C" void kernel_launch(void* const* d_in, const int* in_sizes, int n_in,
                              void* d_out, int out_size) {
    const float* query = (const float*)d_in[0];
    const float* tgt   = (const float*)d_in[1];
    const float* ln1g  = (const float*)d_in[2];
    const float* ln1b  = (const float*)d_in[3];
    const float* ln2g  = (const float*)d_in[4];
    const float* ln2b  = (const float*)d_in[5];
    const float* Wq    = (const float*)d_in[6];
    const float* bq    = (const float*)d_in[7];
    const float* Wk    = (const float*)d_in[8];
    // d_in[9] = bk (cancels in softmax)
    const float* Wv    = (const float*)d_in[10];
    const float* bv    = (const float*)d_in[11];
    const float* Wp    = (const float*)d_in[12];
    const float* bp    = (const float*)d_in[13];
    const float* Wf1   = (const float*)d_in[14];
    const float* bf1   = (const float*)d_in[15];
    const float* Wf2   = (const float*)d_in[16];
    const float* bf2   = (const float*)d_in[17];

    int B = in_sizes[1] / (L * C);
    if (B > MAXB) B = MAXB;

    const int K1_SMEM = (80 * QS + 128 * WVS + 128 + 2 * L * TS + 80 * WSM + 80 * SPS)
                        * sizeof(float);
    const int K2_SMEM = (128 * WS + 2 * 128 * AS + 1024 + 5 * 128) * sizeof(float);

    cudaFuncSetAttribute(attn_kernel, cudaFuncAttributeMaxDynamicSharedMemorySize, K1_SMEM);
    cudaFuncSetAttribute(ffn_kernel,  cudaFuncAttributeMaxDynamicSharedMemorySize, K2_SMEM);

    prep_kernel<<<64, 128>>>(query, ln1g, ln1b, Wq, bq, Wk);
    attn_kernel<<<(B + BPB - 1) / BPB, 512, K1_SMEM>>>(tgt, Wv, bv, B);

    int nrows = B * NTOK;
    ffn_kernel<<<(nrows + 127) / 128, 512, K2_SMEM>>>(query, ln2g, ln2b,
                                                      Wp, bp, Wf1, bf1, Wf2, bf2,
                                                      (float*)d_out, nrows);
}